// round 4
// baseline (speedup 1.0000x reference)
#include <cuda_runtime.h>

// Problem constants
static constexpr int B   = 8;
static constexpr int T   = 1024;
static constexpr int S   = 1024;
static constexpr int H   = 16;
static constexpr int D   = 64;
static constexpr int EMB = 1024;   // H*D
static constexpr int QIN = 1024;
static constexpr int KVIN = 256;
static constexpr float SCALING = 0.125f;  // 64^-0.5

// Scratch (allocation-free rule: __device__ globals)
__device__ float g_Q[B * T * EMB];                 // 32 MB, [b*T+t, h*D+d], pre-scaled
__device__ float g_K[B * S * EMB];                 // 32 MB
__device__ float g_V[B * S * EMB];                 // 32 MB
__device__ float g_ctx[B * T * EMB];               // 32 MB
__device__ float g_P[(size_t)B * H * T * S];       // 512 MB probs/scores

// ---------------------------------------------------------------------------
// Generic NN SGEMM: C[M,N] = (A[M,K] @ Bm[K,N] + bias) * alpha
// Row-major, arbitrary leading dims. Dims must divide tiles (true for all uses).
// ---------------------------------------------------------------------------
template <int BM, int BN, int BK, int TM, int TN>
__global__ __launch_bounds__((BM / TM) * (BN / TN))
void sgemm_nn(int M, int N, int K,
              const float* __restrict__ A, int lda,
              const float* __restrict__ Bm, int ldb,
              float* __restrict__ C, int ldc,
              const float* __restrict__ bias, float alpha)
{
    constexpr int TX = BN / TN, TY = BM / TM, THREADS = TX * TY;
    __shared__ float As[BK][BM + 4];
    __shared__ float Bs[BK][BN + 4];

    const int tid = threadIdx.x;
    const int tx = tid % TX, ty = tid / TX;
    const int row0 = blockIdx.y * BM, col0 = blockIdx.x * BN;

    A  += (size_t)row0 * lda;
    Bm += col0;
    C  += (size_t)row0 * ldc + col0;

    float acc[TM][TN] = {};

    for (int k0 = 0; k0 < K; k0 += BK) {
        // A tile (BM x BK) -> As transposed
        #pragma unroll
        for (int i = tid; i < BM * BK / 4; i += THREADS) {
            int r = i / (BK / 4);
            int c = (i % (BK / 4)) * 4;
            float4 v = *reinterpret_cast<const float4*>(&A[(size_t)r * lda + k0 + c]);
            As[c + 0][r] = v.x; As[c + 1][r] = v.y;
            As[c + 2][r] = v.z; As[c + 3][r] = v.w;
        }
        // B tile (BK x BN)
        #pragma unroll
        for (int i = tid; i < BK * BN / 4; i += THREADS) {
            int r = i / (BN / 4);
            int c = (i % (BN / 4)) * 4;
            *reinterpret_cast<float4*>(&Bs[r][c]) =
                *reinterpret_cast<const float4*>(&Bm[(size_t)(k0 + r) * ldb + c]);
        }
        __syncthreads();

        #pragma unroll
        for (int kk = 0; kk < BK; kk++) {
            float ra[TM], rb[TN];
            #pragma unroll
            for (int i = 0; i < TM; i++) ra[i] = As[kk][ty * TM + i];
            #pragma unroll
            for (int j = 0; j < TN; j++) rb[j] = Bs[kk][tx * TN + j];
            #pragma unroll
            for (int i = 0; i < TM; i++)
                #pragma unroll
                for (int j = 0; j < TN; j++)
                    acc[i][j] += ra[i] * rb[j];
        }
        __syncthreads();
    }

    #pragma unroll
    for (int i = 0; i < TM; i++) {
        int r = ty * TM + i;
        #pragma unroll
        for (int j = 0; j < TN; j++) {
            int c = tx * TN + j;
            float bv = bias ? bias[col0 + c] : 0.0f;
            C[(size_t)r * ldc + c] = (acc[i][j] + bv) * alpha;
        }
    }
}

// ---------------------------------------------------------------------------
// Batched scores: P[z, t, s] = sum_d Q[b,t,h,d] * K[b,s,h,d] + mask[b,t,s]
// z = b*H + h.  NT GEMM (both operands row-major over K dim, contiguous).
// ---------------------------------------------------------------------------
template <int BM, int BN, int BK, int TM, int TN>
__global__ __launch_bounds__((BM / TM) * (BN / TN))
void scores_nt(const float* __restrict__ Q, const float* __restrict__ Kt,
               const float* __restrict__ mask, float* __restrict__ P)
{
    constexpr int TX = BN / TN, TY = BM / TM, THREADS = TX * TY;
    __shared__ float As[BK][BM + 4];
    __shared__ float Bs[BK][BN + 4];

    const int z = blockIdx.z, b = z / H, h = z % H;
    const float* Aq = Q  + (size_t)b * T * EMB + h * D;   // [T, D], ld EMB
    const float* Bk = Kt + (size_t)b * S * EMB + h * D;   // [S, D], ld EMB
    float*       Cz = P  + (size_t)z * T * S;             // [T, S]
    const float* Mz = mask + (size_t)b * T * S;

    const int tid = threadIdx.x;
    const int tx = tid % TX, ty = tid / TX;
    const int row0 = blockIdx.y * BM, col0 = blockIdx.x * BN;

    float acc[TM][TN] = {};

    for (int k0 = 0; k0 < D; k0 += BK) {
        #pragma unroll
        for (int i = tid; i < BM * BK / 4; i += THREADS) {
            int r = i / (BK / 4);
            int c = (i % (BK / 4)) * 4;
            float4 v = *reinterpret_cast<const float4*>(&Aq[(size_t)(row0 + r) * EMB + k0 + c]);
            As[c + 0][r] = v.x; As[c + 1][r] = v.y;
            As[c + 2][r] = v.z; As[c + 3][r] = v.w;
        }
        #pragma unroll
        for (int i = tid; i < BN * BK / 4; i += THREADS) {
            int r = i / (BK / 4);
            int c = (i % (BK / 4)) * 4;
            float4 v = *reinterpret_cast<const float4*>(&Bk[(size_t)(col0 + r) * EMB + k0 + c]);
            Bs[c + 0][r] = v.x; Bs[c + 1][r] = v.y;
            Bs[c + 2][r] = v.z; Bs[c + 3][r] = v.w;
        }
        __syncthreads();

        #pragma unroll
        for (int kk = 0; kk < BK; kk++) {
            float ra[TM], rb[TN];
            #pragma unroll
            for (int i = 0; i < TM; i++) ra[i] = As[kk][ty * TM + i];
            #pragma unroll
            for (int j = 0; j < TN; j++) rb[j] = Bs[kk][tx * TN + j];
            #pragma unroll
            for (int i = 0; i < TM; i++)
                #pragma unroll
                for (int j = 0; j < TN; j++)
                    acc[i][j] += ra[i] * rb[j];
        }
        __syncthreads();
    }

    #pragma unroll
    for (int i = 0; i < TM; i++) {
        int r = row0 + ty * TM + i;
        #pragma unroll
        for (int j = 0; j < TN; j++) {
            int c = col0 + tx * TN + j;
            Cz[(size_t)r * S + c] = acc[i][j] + Mz[(size_t)r * S + c];
        }
    }
}

// ---------------------------------------------------------------------------
// Row softmax over S=1024 + head-mask scale. One block (128 thr) per row.
// ---------------------------------------------------------------------------
__global__ __launch_bounds__(128)
void softmax_rows(float* __restrict__ P, const float* __restrict__ head_mask)
{
    const size_t row = blockIdx.x;            // row = z*T + t, z = b*H + h
    float* p = P + row * S;
    const int h = (int)((row >> 10) & (H - 1));
    const int tid = threadIdx.x;

    __shared__ float red[128];

    float v[8];
    float vmax = -3.4e38f;
    #pragma unroll
    for (int i = 0; i < 8; i++) {
        v[i] = p[tid + i * 128];
        vmax = fmaxf(vmax, v[i]);
    }
    red[tid] = vmax;
    __syncthreads();
    #pragma unroll
    for (int s = 64; s > 0; s >>= 1) {
        if (tid < s) red[tid] = fmaxf(red[tid], red[tid + s]);
        __syncthreads();
    }
    vmax = red[0];
    __syncthreads();

    float sum = 0.0f;
    #pragma unroll
    for (int i = 0; i < 8; i++) {
        v[i] = __expf(v[i] - vmax);
        sum += v[i];
    }
    red[tid] = sum;
    __syncthreads();
    #pragma unroll
    for (int s = 64; s > 0; s >>= 1) {
        if (tid < s) red[tid] += red[tid + s];
        __syncthreads();
    }
    const float scale = head_mask[h] / red[0];
    #pragma unroll
    for (int i = 0; i < 8; i++)
        p[tid + i * 128] = v[i] * scale;
}

// ---------------------------------------------------------------------------
// Batched PV: ctx[b,t,h,d] = sum_s P[z,t,s] * V[b,s,h,d].  NN GEMM, N=D=64.
// ---------------------------------------------------------------------------
template <int BM, int BN, int BK, int TM, int TN>
__global__ __launch_bounds__((BM / TM) * (BN / TN))
void pv_nn(const float* __restrict__ P, const float* __restrict__ V,
           float* __restrict__ ctx)
{
    constexpr int TX = BN / TN, TY = BM / TM, THREADS = TX * TY;
    __shared__ float As[BK][BM + 4];
    __shared__ float Bs[BK][BN + 4];

    const int z = blockIdx.z, b = z / H, h = z % H;
    const float* A  = P   + (size_t)z * T * S;            // [T, S], ld S
    const float* Bv = V   + (size_t)b * S * EMB + h * D;  // [S, D], ld EMB
    float*       C  = ctx + (size_t)b * T * EMB + h * D;  // [T, D], ld EMB

    const int tid = threadIdx.x;
    const int tx = tid % TX, ty = tid / TX;
    const int row0 = blockIdx.y * BM;   // col0 = 0 (N == BN)

    float acc[TM][TN] = {};

    for (int k0 = 0; k0 < S; k0 += BK) {
        #pragma unroll
        for (int i = tid; i < BM * BK / 4; i += THREADS) {
            int r = i / (BK / 4);
            int c = (i % (BK / 4)) * 4;
            float4 v = *reinterpret_cast<const float4*>(&A[(size_t)(row0 + r) * S + k0 + c]);
            As[c + 0][r] = v.x; As[c + 1][r] = v.y;
            As[c + 2][r] = v.z; As[c + 3][r] = v.w;
        }
        #pragma unroll
        for (int i = tid; i < BK * BN / 4; i += THREADS) {
            int r = i / (BN / 4);
            int c = (i % (BN / 4)) * 4;
            *reinterpret_cast<float4*>(&Bs[r][c]) =
                *reinterpret_cast<const float4*>(&Bv[(size_t)(k0 + r) * EMB + c]);
        }
        __syncthreads();

        #pragma unroll
        for (int kk = 0; kk < BK; kk++) {
            float ra[TM], rb[TN];
            #pragma unroll
            for (int i = 0; i < TM; i++) ra[i] = As[kk][ty * TM + i];
            #pragma unroll
            for (int j = 0; j < TN; j++) rb[j] = Bs[kk][tx * TN + j];
            #pragma unroll
            for (int i = 0; i < TM; i++)
                #pragma unroll
                for (int j = 0; j < TN; j++)
                    acc[i][j] += ra[i] * rb[j];
        }
        __syncthreads();
    }

    #pragma unroll
    for (int i = 0; i < TM; i++) {
        int r = row0 + ty * TM + i;
        #pragma unroll
        for (int j = 0; j < TN; j++) {
            int c = tx * TN + j;
            C[(size_t)r * EMB + c] = acc[i][j];
        }
    }
}

// ---------------------------------------------------------------------------
extern "C" void kernel_launch(void* const* d_in, const int* in_sizes, int n_in,
                              void* d_out, int out_size)
{
    const float* hs   = (const float*)d_in[0];   // [8,1024,1024]
    const float* kv   = (const float*)d_in[1];   // [8,1024,256]
    const float* mask = (const float*)d_in[2];   // [8,1,1024,1024]
    const float* hm   = (const float*)d_in[3];   // [16]
    const float* Wq   = (const float*)d_in[4];
    const float* bq   = (const float*)d_in[5];
    const float* Wk   = (const float*)d_in[6];
    const float* bk   = (const float*)d_in[7];
    const float* Wv   = (const float*)d_in[8];
    const float* bv   = (const float*)d_in[9];
    const float* Wo   = (const float*)d_in[10];
    const float* bo   = (const float*)d_in[11];
    float* out = (float*)d_out;

    float *Qp, *Kp, *Vp, *Pp, *Cp;
    cudaGetSymbolAddress((void**)&Qp, g_Q);
    cudaGetSymbolAddress((void**)&Kp, g_K);
    cudaGetSymbolAddress((void**)&Vp, g_V);
    cudaGetSymbolAddress((void**)&Pp, g_P);
    cudaGetSymbolAddress((void**)&Cp, g_ctx);

    // Q = (hs @ Wq + bq) * scaling   [8192,1024] x [1024,1024]
    sgemm_nn<128, 128, 8, 8, 8><<<dim3(EMB / 128, (B * T) / 128), 256>>>(
        B * T, EMB, QIN, hs, QIN, Wq, EMB, Qp, EMB, bq, SCALING);

    // K = kv @ Wk + bk   [8192,256] x [256,1024]
    sgemm_nn<128, 128, 8, 8, 8><<<dim3(EMB / 128, (B * S) / 128), 256>>>(
        B * S, EMB, KVIN, kv, KVIN, Wk, EMB, Kp, EMB, bk, 1.0f);

    // V = kv @ Wv + bv
    sgemm_nn<128, 128, 8, 8, 8><<<dim3(EMB / 128, (B * S) / 128), 256>>>(
        B * S, EMB, KVIN, kv, KVIN, Wv, EMB, Vp, EMB, bv, 1.0f);

    // scores = Q @ K^T + mask   (batched over b*h)
    scores_nt<128, 128, 16, 8, 8><<<dim3(S / 128, T / 128, B * H), 256>>>(
        Qp, Kp, mask, Pp);

    // softmax rows + head mask
    softmax_rows<<<B * H * T, 128>>>(Pp, hm);

    // ctx = P @ V  (batched)
    pv_nn<128, 64, 16, 8, 4><<<dim3(1, T / 128, B * H), 256>>>(Pp, Vp, Cp);

    // out = ctx @ Wo + bo
    sgemm_nn<128, 128, 8, 8, 8><<<dim3(EMB / 128, (B * T) / 128), 256>>>(
        B * T, EMB, EMB, Cp, EMB, Wo, EMB, out, EMB, bo, 1.0f);
}

// round 5
// speedup vs baseline: 1.6786x; 1.6786x over previous
#include <cuda_runtime.h>
#include <cuda_bf16.h>
#include <cstdint>

// Problem constants
static constexpr int B   = 8;
static constexpr int T   = 1024;
static constexpr int S   = 1024;
static constexpr int H   = 16;
static constexpr int D   = 64;
static constexpr int EMB = 1024;
static constexpr int QIN = 1024;
static constexpr int KVIN = 256;
static constexpr float SCALING = 0.125f;

// ---------------------------------------------------------------------------
// Scratch (__device__ globals; allocation-free rule)
// ---------------------------------------------------------------------------
__device__ float g_P[(size_t)B * H * T * S];                  // 512 MB scores/probs

__device__ __nv_bfloat16 g_Qhi[B * T * EMB], g_Qlo[B * T * EMB];
__device__ __nv_bfloat16 g_Khi[B * S * EMB], g_Klo[B * S * EMB];
__device__ __nv_bfloat16 g_Vhi[B * S * EMB], g_Vlo[B * S * EMB];
__device__ __nv_bfloat16 g_Vthi[B * H * D * S], g_Vtlo[B * H * D * S];   // [z*D+d][S]
__device__ __nv_bfloat16 g_Chi[B * T * EMB], g_Clo[B * T * EMB];         // ctx

__device__ __nv_bfloat16 g_Wqthi[EMB * QIN],  g_Wqtlo[EMB * QIN];        // [N][K]
__device__ __nv_bfloat16 g_Wkthi[EMB * KVIN], g_Wktlo[EMB * KVIN];
__device__ __nv_bfloat16 g_Wvthi[EMB * KVIN], g_Wvtlo[EMB * KVIN];
__device__ __nv_bfloat16 g_Wothi[EMB * EMB],  g_Wotlo[EMB * EMB];

// ---------------------------------------------------------------------------
// Helpers
// ---------------------------------------------------------------------------
static constexpr int LDSS = 40;   // smem row stride (bf16 elems) for 32-col tiles

__device__ __forceinline__ uint32_t ld32(const __nv_bfloat16* p) {
    return *reinterpret_cast<const uint32_t*>(p);
}

__device__ __forceinline__ void mma16816(float* c, const uint32_t* a, const uint32_t* b) {
    asm volatile(
        "mma.sync.aligned.m16n8k16.row.col.f32.bf16.bf16.f32 "
        "{%0,%1,%2,%3}, {%4,%5,%6,%7}, {%8,%9}, {%0,%1,%2,%3};\n"
        : "+f"(c[0]), "+f"(c[1]), "+f"(c[2]), "+f"(c[3])
        : "r"(a[0]), "r"(a[1]), "r"(a[2]), "r"(a[3]), "r"(b[0]), "r"(b[1]));
}

// split two floats into packed bf16x2 hi / lo words
__device__ __forceinline__ void split2(float v0, float v1, uint32_t& hi, uint32_t& lo) {
    __nv_bfloat16 h0 = __float2bfloat16(v0), h1 = __float2bfloat16(v1);
    __nv_bfloat16 l0 = __float2bfloat16(v0 - __bfloat162float(h0));
    __nv_bfloat16 l1 = __float2bfloat16(v1 - __bfloat162float(h1));
    __nv_bfloat162 hp; hp.x = h0; hp.y = h1;
    __nv_bfloat162 lp; lp.x = l0; lp.y = l1;
    hi = *reinterpret_cast<uint32_t*>(&hp);
    lo = *reinterpret_cast<uint32_t*>(&lp);
}

// Stage a pre-split bf16 tile [ROWS x 32] (row stride ld) into smem (stride LDSS)
template <int ROWS, int THREADS>
__device__ __forceinline__ void stage_bf16(const __nv_bfloat16* __restrict__ src, size_t ld,
                                           __nv_bfloat16* __restrict__ dst, int tid)
{
    #pragma unroll
    for (int i = tid; i < ROWS * 8; i += THREADS) {
        int r = i >> 3, c4 = i & 7;
        *reinterpret_cast<uint2*>(&dst[r * LDSS + c4 * 4]) =
            *reinterpret_cast<const uint2*>(&src[(size_t)r * ld + c4 * 4]);
    }
}

// Stage an fp32 tile [ROWS x 32], converting to bf16 hi/lo
template <int ROWS, int THREADS>
__device__ __forceinline__ void stage_f32(const float* __restrict__ src, size_t ld,
                                          __nv_bfloat16* __restrict__ dh,
                                          __nv_bfloat16* __restrict__ dl, int tid)
{
    #pragma unroll
    for (int i = tid; i < ROWS * 8; i += THREADS) {
        int r = i >> 3, c4 = i & 7;
        float4 v = *reinterpret_cast<const float4*>(&src[(size_t)r * ld + c4 * 4]);
        float vv[4] = {v.x, v.y, v.z, v.w};
        __align__(8) __nv_bfloat16 h[4], l[4];
        #pragma unroll
        for (int j = 0; j < 4; j++) {
            h[j] = __float2bfloat16(vv[j]);
            l[j] = __float2bfloat16(vv[j] - __bfloat162float(h[j]));
        }
        *reinterpret_cast<uint2*>(&dh[r * LDSS + c4 * 4]) = *reinterpret_cast<uint2*>(h);
        *reinterpret_cast<uint2*>(&dl[r * LDSS + c4 * 4]) = *reinterpret_cast<uint2*>(l);
    }
}

// One BK=32 iteration of split-bf16 MMA. acc[MT][NT][4] fp32.
template <int MT, int NT>
__device__ __forceinline__ void mma_iter(const __nv_bfloat16* __restrict__ As_h,
                                         const __nv_bfloat16* __restrict__ As_l,
                                         const __nv_bfloat16* __restrict__ Bs_h,
                                         const __nv_bfloat16* __restrict__ Bs_l,
                                         int am0, int bn0, int lane,
                                         float (*acc)[NT][4])
{
    #pragma unroll
    for (int ks = 0; ks < 2; ks++) {
        uint32_t ah[MT][4], al[MT][4];
        #pragma unroll
        for (int mt = 0; mt < MT; mt++) {
            int r = am0 + mt * 16 + (lane >> 2);
            int c = ks * 16 + (lane & 3) * 2;
            const __nv_bfloat16* p = As_h + r * LDSS + c;
            ah[mt][0] = ld32(p);
            ah[mt][1] = ld32(p + 8 * LDSS);
            ah[mt][2] = ld32(p + 8);
            ah[mt][3] = ld32(p + 8 * LDSS + 8);
            p = As_l + r * LDSS + c;
            al[mt][0] = ld32(p);
            al[mt][1] = ld32(p + 8 * LDSS);
            al[mt][2] = ld32(p + 8);
            al[mt][3] = ld32(p + 8 * LDSS + 8);
        }
        uint32_t bh[NT][2], bl[NT][2];
        #pragma unroll
        for (int nt = 0; nt < NT; nt++) {
            int n = bn0 + nt * 8 + (lane >> 2);
            int c = ks * 16 + (lane & 3) * 2;
            bh[nt][0] = ld32(Bs_h + n * LDSS + c);
            bh[nt][1] = ld32(Bs_h + n * LDSS + c + 8);
            bl[nt][0] = ld32(Bs_l + n * LDSS + c);
            bl[nt][1] = ld32(Bs_l + n * LDSS + c + 8);
        }
        #pragma unroll
        for (int mt = 0; mt < MT; mt++)
            #pragma unroll
            for (int nt = 0; nt < NT; nt++) {
                mma16816(acc[mt][nt], ah[mt], bh[nt]);   // hi*hi
                mma16816(acc[mt][nt], ah[mt], bl[nt]);   // hi*lo
                mma16816(acc[mt][nt], al[mt], bh[nt]);   // lo*hi
            }
    }
}

// ---------------------------------------------------------------------------
// Weight transpose + split: W [K,N] fp32 -> Wt_hi/lo [N,K] bf16
// ---------------------------------------------------------------------------
__global__ __launch_bounds__(256)
void wsplit_t(const float* __restrict__ W, int K, int N,
              __nv_bfloat16* __restrict__ Whi, __nv_bfloat16* __restrict__ Wlo)
{
    __shared__ float sm[32][33];
    const int k0 = blockIdx.y * 32, n0 = blockIdx.x * 32;
    const int tid = threadIdx.x;

    for (int i = tid; i < 32 * 8; i += 256) {
        int r = i >> 3, c4 = i & 7;
        float4 v = *reinterpret_cast<const float4*>(&W[(size_t)(k0 + r) * N + n0 + c4 * 4]);
        sm[r][c4 * 4 + 0] = v.x; sm[r][c4 * 4 + 1] = v.y;
        sm[r][c4 * 4 + 2] = v.z; sm[r][c4 * 4 + 3] = v.w;
    }
    __syncthreads();
    for (int i = tid; i < 32 * 8; i += 256) {
        int n = i >> 3, k4 = i & 7;
        __align__(8) __nv_bfloat16 h[4], l[4];
        #pragma unroll
        for (int j = 0; j < 4; j++) {
            float v = sm[k4 * 4 + j][n];
            h[j] = __float2bfloat16(v);
            l[j] = __float2bfloat16(v - __bfloat162float(h[j]));
        }
        *reinterpret_cast<uint2*>(&Whi[(size_t)(n0 + n) * K + k0 + k4 * 4]) = *reinterpret_cast<uint2*>(h);
        *reinterpret_cast<uint2*>(&Wlo[(size_t)(n0 + n) * K + k0 + k4 * 4]) = *reinterpret_cast<uint2*>(l);
    }
}

// ---------------------------------------------------------------------------
// V transpose (bf16): V [b*S+s][h*D+d] -> Vt [(b*H+h)*D+d][s]
// ---------------------------------------------------------------------------
__global__ __launch_bounds__(256)
void vtrans(const __nv_bfloat16* __restrict__ Vh, const __nv_bfloat16* __restrict__ Vl,
            __nv_bfloat16* __restrict__ Vth, __nv_bfloat16* __restrict__ Vtl)
{
    __shared__ __nv_bfloat16 sm[64][72];
    const int z = blockIdx.z, bb = z >> 4, hh = z & 15;
    const int s0 = blockIdx.x * 64;

    #pragma unroll
    for (int p = 0; p < 2; p++) {
        const __nv_bfloat16* src = p ? Vl : Vh;
        __nv_bfloat16* dst = p ? Vtl : Vth;
        const __nv_bfloat16* sp = src + (size_t)(bb * S + s0) * EMB + hh * D;
        for (int i = threadIdx.x; i < 64 * 16; i += 256) {
            int s = i >> 4, d4 = i & 15;
            *reinterpret_cast<uint2*>(&sm[s][d4 * 4]) =
                *reinterpret_cast<const uint2*>(&sp[(size_t)s * EMB + d4 * 4]);
        }
        __syncthreads();
        __nv_bfloat16* dp = dst + (size_t)z * D * S + s0;
        for (int i = threadIdx.x; i < 64 * 16; i += 256) {
            int d = i >> 4, s4 = i & 15;
            __align__(8) __nv_bfloat16 t[4];
            t[0] = sm[s4 * 4 + 0][d]; t[1] = sm[s4 * 4 + 1][d];
            t[2] = sm[s4 * 4 + 2][d]; t[3] = sm[s4 * 4 + 3][d];
            *reinterpret_cast<uint2*>(&dp[(size_t)d * S + s4 * 4]) = *reinterpret_cast<uint2*>(t);
        }
        __syncthreads();
    }
}

// ---------------------------------------------------------------------------
// Projection GEMM (NT): C[M,N] = (A[M,K] @ Bt[N,K]^T + bias) * alpha
// A: fp32 (A_SPLIT=0) or pre-split bf16 (A_SPLIT=1).
// Output: fp32 (OUT_SPLIT=0) or split bf16 pair (OUT_SPLIT=1).
// BM=128, BN=128, 256 threads, warps 2x4.
// ---------------------------------------------------------------------------
template <bool A_SPLIT, bool OUT_SPLIT>
__global__ __launch_bounds__(256)
void proj_nt(int K,
             const float* __restrict__ Af,
             const __nv_bfloat16* __restrict__ Ah, const __nv_bfloat16* __restrict__ Al,
             int lda,
             const __nv_bfloat16* __restrict__ Bth, const __nv_bfloat16* __restrict__ Btl,
             float* __restrict__ Cf,
             __nv_bfloat16* __restrict__ Ch, __nv_bfloat16* __restrict__ Cl,
             int ldc, const float* __restrict__ bias, float alpha)
{
    __shared__ __nv_bfloat16 Ash[128 * LDSS], Asl[128 * LDSS];
    __shared__ __nv_bfloat16 Bsh[128 * LDSS], Bsl[128 * LDSS];

    const int tid = threadIdx.x, lane = tid & 31, wid = tid >> 5;
    const int wm = wid >> 2, wn = wid & 3;             // 2 x 4 warps
    const int row0 = blockIdx.y * 128, col0 = blockIdx.x * 128;

    float acc[4][4][4] = {};

    for (int k0 = 0; k0 < K; k0 += 32) {
        if (A_SPLIT) {
            stage_bf16<128, 256>(Ah + (size_t)row0 * lda + k0, lda, Ash, tid);
            stage_bf16<128, 256>(Al + (size_t)row0 * lda + k0, lda, Asl, tid);
        } else {
            stage_f32<128, 256>(Af + (size_t)row0 * lda + k0, lda, Ash, Asl, tid);
        }
        stage_bf16<128, 256>(Bth + (size_t)col0 * K + k0, K, Bsh, tid);
        stage_bf16<128, 256>(Btl + (size_t)col0 * K + k0, K, Bsl, tid);
        __syncthreads();
        mma_iter<4, 4>(Ash, Asl, Bsh, Bsl, wm * 64, wn * 32, lane, acc);
        __syncthreads();
    }

    #pragma unroll
    for (int mt = 0; mt < 4; mt++)
        #pragma unroll
        for (int nt = 0; nt < 4; nt++) {
            int r0 = row0 + wm * 64 + mt * 16 + (lane >> 2);
            int cc = col0 + wn * 32 + nt * 8 + ((lane & 3) << 1);
            float b0 = bias[cc], b1 = bias[cc + 1];
            #pragma unroll
            for (int half = 0; half < 2; half++) {
                int r = r0 + half * 8;
                float v0 = (acc[mt][nt][half * 2 + 0] + b0) * alpha;
                float v1 = (acc[mt][nt][half * 2 + 1] + b1) * alpha;
                if (OUT_SPLIT) {
                    uint32_t hi, lo;
                    split2(v0, v1, hi, lo);
                    *reinterpret_cast<uint32_t*>(&Ch[(size_t)r * ldc + cc]) = hi;
                    *reinterpret_cast<uint32_t*>(&Cl[(size_t)r * ldc + cc]) = lo;
                } else {
                    float2 o; o.x = v0; o.y = v1;
                    *reinterpret_cast<float2*>(&Cf[(size_t)r * ldc + cc]) = o;
                }
            }
        }
}

// ---------------------------------------------------------------------------
// Scores (NT, batched z=b*H+h): P[z,t,s] = Q[t,:] . K[s,:] + mask[b,t,s]
// Q/K pre-split bf16, [rows][EMB] with head offset. K(dim)=64.
// ---------------------------------------------------------------------------
__global__ __launch_bounds__(256)
void scores_mm(const __nv_bfloat16* __restrict__ Qh, const __nv_bfloat16* __restrict__ Ql,
               const __nv_bfloat16* __restrict__ Kh, const __nv_bfloat16* __restrict__ Kl,
               const float* __restrict__ mask, float* __restrict__ P)
{
    __shared__ __nv_bfloat16 Ash[128 * LDSS], Asl[128 * LDSS];
    __shared__ __nv_bfloat16 Bsh[128 * LDSS], Bsl[128 * LDSS];

    const int tid = threadIdx.x, lane = tid & 31, wid = tid >> 5;
    const int wm = wid >> 2, wn = wid & 3;
    const int z = blockIdx.z, bb = z >> 4, hh = z & 15;
    const int row0 = blockIdx.y * 128, col0 = blockIdx.x * 128;

    const size_t qoff = (size_t)bb * T * EMB + hh * D;
    const size_t koff = (size_t)bb * S * EMB + hh * D;
    float* Cz = P + (size_t)z * T * S;
    const float* Mz = mask + (size_t)bb * T * S;

    float acc[4][4][4] = {};

    #pragma unroll
    for (int k0 = 0; k0 < D; k0 += 32) {
        stage_bf16<128, 256>(Qh + qoff + (size_t)row0 * EMB + k0, EMB, Ash, tid);
        stage_bf16<128, 256>(Ql + qoff + (size_t)row0 * EMB + k0, EMB, Asl, tid);
        stage_bf16<128, 256>(Kh + koff + (size_t)col0 * EMB + k0, EMB, Bsh, tid);
        stage_bf16<128, 256>(Kl + koff + (size_t)col0 * EMB + k0, EMB, Bsl, tid);
        __syncthreads();
        mma_iter<4, 4>(Ash, Asl, Bsh, Bsl, wm * 64, wn * 32, lane, acc);
        __syncthreads();
    }

    #pragma unroll
    for (int mt = 0; mt < 4; mt++)
        #pragma unroll
        for (int nt = 0; nt < 4; nt++) {
            int r0 = row0 + wm * 64 + mt * 16 + (lane >> 2);
            int cc = col0 + wn * 32 + nt * 8 + ((lane & 3) << 1);
            #pragma unroll
            for (int half = 0; half < 2; half++) {
                int r = r0 + half * 8;
                float2 m = *reinterpret_cast<const float2*>(&Mz[(size_t)r * S + cc]);
                float2 o;
                o.x = acc[mt][nt][half * 2 + 0] + m.x;
                o.y = acc[mt][nt][half * 2 + 1] + m.y;
                *reinterpret_cast<float2*>(&Cz[(size_t)r * S + cc]) = o;
            }
        }
}

// ---------------------------------------------------------------------------
// Row softmax over S=1024 + head-mask scale (fp32 in/out)
// ---------------------------------------------------------------------------
__global__ __launch_bounds__(128)
void softmax_rows(float* __restrict__ P, const float* __restrict__ head_mask)
{
    const size_t row = blockIdx.x;
    float* p = P + row * S;
    const int h = (int)((row >> 10) & (H - 1));
    const int tid = threadIdx.x;

    __shared__ float red[128];

    float v[8];
    float vmax = -3.4e38f;
    #pragma unroll
    for (int i = 0; i < 8; i++) {
        v[i] = p[tid + i * 128];
        vmax = fmaxf(vmax, v[i]);
    }
    red[tid] = vmax;
    __syncthreads();
    #pragma unroll
    for (int s = 64; s > 0; s >>= 1) {
        if (tid < s) red[tid] = fmaxf(red[tid], red[tid + s]);
        __syncthreads();
    }
    vmax = red[0];
    __syncthreads();

    float sum = 0.0f;
    #pragma unroll
    for (int i = 0; i < 8; i++) {
        v[i] = __expf(v[i] - vmax);
        sum += v[i];
    }
    red[tid] = sum;
    __syncthreads();
    #pragma unroll
    for (int s = 64; s > 0; s >>= 1) {
        if (tid < s) red[tid] += red[tid + s];
        __syncthreads();
    }
    const float scale = head_mask[h] / red[0];
    #pragma unroll
    for (int i = 0; i < 8; i++)
        p[tid + i * 128] = v[i] * scale;
}

// ---------------------------------------------------------------------------
// PV (NT, batched): ctx[t, d] = sum_s P[z,t,s] * Vt[z*D+d, s]
// BM=128, BN=64, warps 4x2 (warp tile 32x32): MT=2, NT=4.
// Output: split bf16 ctx.
// ---------------------------------------------------------------------------
__global__ __launch_bounds__(256)
void pv_mm(const float* __restrict__ P,
           const __nv_bfloat16* __restrict__ Vth, const __nv_bfloat16* __restrict__ Vtl,
           __nv_bfloat16* __restrict__ Ch, __nv_bfloat16* __restrict__ Cl)
{
    __shared__ __nv_bfloat16 Ash[128 * LDSS], Asl[128 * LDSS];
    __shared__ __nv_bfloat16 Bsh[64 * LDSS], Bsl[64 * LDSS];

    const int tid = threadIdx.x, lane = tid & 31, wid = tid >> 5;
    const int wm = wid >> 1, wn = wid & 1;             // 4 x 2 warps
    const int z = blockIdx.z, bb = z >> 4, hh = z & 15;
    const int row0 = blockIdx.y * 128;

    const float* A = P + (size_t)z * T * S + (size_t)row0 * S;
    const __nv_bfloat16* Bh = Vth + (size_t)z * D * S;
    const __nv_bfloat16* Bl = Vtl + (size_t)z * D * S;

    float acc[2][4][4] = {};

    for (int k0 = 0; k0 < S; k0 += 32) {
        stage_f32<128, 256>(A + k0, S, Ash, Asl, tid);
        stage_bf16<64, 256>(Bh + k0, S, Bsh, tid);
        stage_bf16<64, 256>(Bl + k0, S, Bsl, tid);
        __syncthreads();
        mma_iter<2, 4>(Ash, Asl, Bsh, Bsl, wm * 32, wn * 32, lane, acc);
        __syncthreads();
    }

    __nv_bfloat16* Cho = Ch + (size_t)bb * T * EMB + hh * D;
    __nv_bfloat16* Clo = Cl + (size_t)bb * T * EMB + hh * D;

    #pragma unroll
    for (int mt = 0; mt < 2; mt++)
        #pragma unroll
        for (int nt = 0; nt < 4; nt++) {
            int r0 = row0 + wm * 32 + mt * 16 + (lane >> 2);
            int cc = wn * 32 + nt * 8 + ((lane & 3) << 1);
            #pragma unroll
            for (int half = 0; half < 2; half++) {
                int r = r0 + half * 8;
                uint32_t hi, lo;
                split2(acc[mt][nt][half * 2 + 0], acc[mt][nt][half * 2 + 1], hi, lo);
                *reinterpret_cast<uint32_t*>(&Cho[(size_t)r * EMB + cc]) = hi;
                *reinterpret_cast<uint32_t*>(&Clo[(size_t)r * EMB + cc]) = lo;
            }
        }
}

// ---------------------------------------------------------------------------
extern "C" void kernel_launch(void* const* d_in, const int* in_sizes, int n_in,
                              void* d_out, int out_size)
{
    const float* hs   = (const float*)d_in[0];
    const float* kv   = (const float*)d_in[1];
    const float* mask = (const float*)d_in[2];
    const float* hm   = (const float*)d_in[3];
    const float* Wq   = (const float*)d_in[4];
    const float* bq   = (const float*)d_in[5];
    const float* Wk   = (const float*)d_in[6];
    const float* bk   = (const float*)d_in[7];
    const float* Wv   = (const float*)d_in[8];
    const float* bv   = (const float*)d_in[9];
    const float* Wo   = (const float*)d_in[10];
    const float* bo   = (const float*)d_in[11];
    float* out = (float*)d_out;

    float* Pp;
    __nv_bfloat16 *Qh, *Ql, *Kh, *Kl, *Vh, *Vl, *Vth, *Vtl, *Ch, *Cl;
    __nv_bfloat16 *Wqh, *Wql, *Wkh, *Wkl, *Wvh, *Wvl, *Woh, *Wol;
    cudaGetSymbolAddress((void**)&Pp, g_P);
    cudaGetSymbolAddress((void**)&Qh, g_Qhi);  cudaGetSymbolAddress((void**)&Ql, g_Qlo);
    cudaGetSymbolAddress((void**)&Kh, g_Khi);  cudaGetSymbolAddress((void**)&Kl, g_Klo);
    cudaGetSymbolAddress((void**)&Vh, g_Vhi);  cudaGetSymbolAddress((void**)&Vl, g_Vlo);
    cudaGetSymbolAddress((void**)&Vth, g_Vthi); cudaGetSymbolAddress((void**)&Vtl, g_Vtlo);
    cudaGetSymbolAddress((void**)&Ch, g_Chi);  cudaGetSymbolAddress((void**)&Cl, g_Clo);
    cudaGetSymbolAddress((void**)&Wqh, g_Wqthi); cudaGetSymbolAddress((void**)&Wql, g_Wqtlo);
    cudaGetSymbolAddress((void**)&Wkh, g_Wkthi); cudaGetSymbolAddress((void**)&Wkl, g_Wktlo);
    cudaGetSymbolAddress((void**)&Wvh, g_Wvthi); cudaGetSymbolAddress((void**)&Wvl, g_Wvtlo);
    cudaGetSymbolAddress((void**)&Woh, g_Wothi); cudaGetSymbolAddress((void**)&Wol, g_Wotlo);

    // Weight transpose + split
    wsplit_t<<<dim3(EMB / 32, QIN / 32), 256>>>(Wq, QIN, EMB, Wqh, Wql);
    wsplit_t<<<dim3(EMB / 32, KVIN / 32), 256>>>(Wk, KVIN, EMB, Wkh, Wkl);
    wsplit_t<<<dim3(EMB / 32, KVIN / 32), 256>>>(Wv, KVIN, EMB, Wvh, Wvl);
    wsplit_t<<<dim3(EMB / 32, EMB / 32), 256>>>(Wo, EMB, EMB, Woh, Wol);

    // Q = (hs @ Wq + bq) * scaling   -> split
    proj_nt<false, true><<<dim3(EMB / 128, (B * T) / 128), 256>>>(
        QIN, hs, nullptr, nullptr, QIN, Wqh, Wql,
        nullptr, Qh, Ql, EMB, bq, SCALING);
    // K, V projections -> split
    proj_nt<false, true><<<dim3(EMB / 128, (B * S) / 128), 256>>>(
        KVIN, kv, nullptr, nullptr, KVIN, Wkh, Wkl,
        nullptr, Kh, Kl, EMB, bk, 1.0f);
    proj_nt<false, true><<<dim3(EMB / 128, (B * S) / 128), 256>>>(
        KVIN, kv, nullptr, nullptr, KVIN, Wvh, Wvl,
        nullptr, Vh, Vl, EMB, bv, 1.0f);

    // V transpose per head
    vtrans<<<dim3(S / 64, 1, B * H), 256>>>(Vh, Vl, Vth, Vtl);

    // scores = Q @ K^T + mask
    scores_mm<<<dim3(S / 128, T / 128, B * H), 256>>>(Qh, Ql, Kh, Kl, mask, Pp);

    // softmax + head mask
    softmax_rows<<<B * H * T, 128>>>(Pp, hm);

    // ctx = P @ V -> split
    pv_mm<<<dim3(1, T / 128, B * H), 256>>>(Pp, Vth, Vtl, Ch, Cl);

    // out = ctx @ Wo + bo
    proj_nt<true, false><<<dim3(EMB / 128, (B * T) / 128), 256>>>(
        EMB, nullptr, Ch, Cl, EMB, Woh, Wol,
        out, nullptr, nullptr, EMB, bo, 1.0f);
}

// round 6
// speedup vs baseline: 2.1472x; 1.2792x over previous
#include <cuda_runtime.h>
#include <cuda_bf16.h>
#include <cstdint>

// Problem constants
static constexpr int B   = 8;
static constexpr int T   = 1024;
static constexpr int S   = 1024;
static constexpr int H   = 16;
static constexpr int D   = 64;
static constexpr int EMB = 1024;
static constexpr int QIN = 1024;
static constexpr int KVIN = 256;
static constexpr float SCALING = 0.125f;

// ---------------------------------------------------------------------------
// Scratch (__device__ globals; allocation-free rule)
// ---------------------------------------------------------------------------
__device__ __nv_bfloat16 g_Qhi[B * T * EMB], g_Qlo[B * T * EMB];
__device__ __nv_bfloat16 g_Khi[B * S * EMB], g_Klo[B * S * EMB];
__device__ __nv_bfloat16 g_Vhi[B * S * EMB], g_Vlo[B * S * EMB];
__device__ __nv_bfloat16 g_Vthi[B * H * D * S], g_Vtlo[B * H * D * S];   // [z*D+d][S]
__device__ __nv_bfloat16 g_Chi[B * T * EMB], g_Clo[B * T * EMB];         // ctx

__device__ __nv_bfloat16 g_Wqthi[EMB * QIN],  g_Wqtlo[EMB * QIN];        // [N][K]
__device__ __nv_bfloat16 g_Wkthi[EMB * KVIN], g_Wktlo[EMB * KVIN];
__device__ __nv_bfloat16 g_Wvthi[EMB * KVIN], g_Wvtlo[EMB * KVIN];
__device__ __nv_bfloat16 g_Wothi[EMB * EMB],  g_Wotlo[EMB * EMB];

// ---------------------------------------------------------------------------
// Helpers
// ---------------------------------------------------------------------------
static constexpr int LDSS = 40;   // smem row stride (bf16) for 32-col proj tiles

__device__ __forceinline__ uint32_t ld32(const __nv_bfloat16* p) {
    return *reinterpret_cast<const uint32_t*>(p);
}

__device__ __forceinline__ void mma16816(float* c, const uint32_t* a, const uint32_t* b) {
    asm volatile(
        "mma.sync.aligned.m16n8k16.row.col.f32.bf16.bf16.f32 "
        "{%0,%1,%2,%3}, {%4,%5,%6,%7}, {%8,%9}, {%0,%1,%2,%3};\n"
        : "+f"(c[0]), "+f"(c[1]), "+f"(c[2]), "+f"(c[3])
        : "r"(a[0]), "r"(a[1]), "r"(a[2]), "r"(a[3]), "r"(b[0]), "r"(b[1]));
}

__device__ __forceinline__ void split2(float v0, float v1, uint32_t& hi, uint32_t& lo) {
    __nv_bfloat16 h0 = __float2bfloat16(v0), h1 = __float2bfloat16(v1);
    __nv_bfloat16 l0 = __float2bfloat16(v0 - __bfloat162float(h0));
    __nv_bfloat16 l1 = __float2bfloat16(v1 - __bfloat162float(h1));
    __nv_bfloat162 hp; hp.x = h0; hp.y = h1;
    __nv_bfloat162 lp; lp.x = l0; lp.y = l1;
    hi = *reinterpret_cast<uint32_t*>(&hp);
    lo = *reinterpret_cast<uint32_t*>(&lp);
}

template <int ROWS, int THREADS>
__device__ __forceinline__ void stage_bf16(const __nv_bfloat16* __restrict__ src, size_t ld,
                                           __nv_bfloat16* __restrict__ dst, int tid)
{
    #pragma unroll
    for (int i = tid; i < ROWS * 8; i += THREADS) {
        int r = i >> 3, c4 = i & 7;
        *reinterpret_cast<uint2*>(&dst[r * LDSS + c4 * 4]) =
            *reinterpret_cast<const uint2*>(&src[(size_t)r * ld + c4 * 4]);
    }
}

template <int ROWS, int THREADS>
__device__ __forceinline__ void stage_f32(const float* __restrict__ src, size_t ld,
                                          __nv_bfloat16* __restrict__ dh,
                                          __nv_bfloat16* __restrict__ dl, int tid)
{
    #pragma unroll
    for (int i = tid; i < ROWS * 8; i += THREADS) {
        int r = i >> 3, c4 = i & 7;
        float4 v = *reinterpret_cast<const float4*>(&src[(size_t)r * ld + c4 * 4]);
        float vv[4] = {v.x, v.y, v.z, v.w};
        __align__(8) __nv_bfloat16 h[4], l[4];
        #pragma unroll
        for (int j = 0; j < 4; j++) {
            h[j] = __float2bfloat16(vv[j]);
            l[j] = __float2bfloat16(vv[j] - __bfloat162float(h[j]));
        }
        *reinterpret_cast<uint2*>(&dh[r * LDSS + c4 * 4]) = *reinterpret_cast<uint2*>(h);
        *reinterpret_cast<uint2*>(&dl[r * LDSS + c4 * 4]) = *reinterpret_cast<uint2*>(l);
    }
}

template <int MT, int NT>
__device__ __forceinline__ void mma_iter(const __nv_bfloat16* __restrict__ As_h,
                                         const __nv_bfloat16* __restrict__ As_l,
                                         const __nv_bfloat16* __restrict__ Bs_h,
                                         const __nv_bfloat16* __restrict__ Bs_l,
                                         int am0, int bn0, int lane,
                                         float (*acc)[NT][4])
{
    #pragma unroll
    for (int ks = 0; ks < 2; ks++) {
        uint32_t ah[MT][4], al[MT][4];
        #pragma unroll
        for (int mt = 0; mt < MT; mt++) {
            int r = am0 + mt * 16 + (lane >> 2);
            int c = ks * 16 + (lane & 3) * 2;
            const __nv_bfloat16* p = As_h + r * LDSS + c;
            ah[mt][0] = ld32(p);
            ah[mt][1] = ld32(p + 8 * LDSS);
            ah[mt][2] = ld32(p + 8);
            ah[mt][3] = ld32(p + 8 * LDSS + 8);
            p = As_l + r * LDSS + c;
            al[mt][0] = ld32(p);
            al[mt][1] = ld32(p + 8 * LDSS);
            al[mt][2] = ld32(p + 8);
            al[mt][3] = ld32(p + 8 * LDSS + 8);
        }
        uint32_t bh[NT][2], bl[NT][2];
        #pragma unroll
        for (int nt = 0; nt < NT; nt++) {
            int n = bn0 + nt * 8 + (lane >> 2);
            int c = ks * 16 + (lane & 3) * 2;
            bh[nt][0] = ld32(Bs_h + n * LDSS + c);
            bh[nt][1] = ld32(Bs_h + n * LDSS + c + 8);
            bl[nt][0] = ld32(Bs_l + n * LDSS + c);
            bl[nt][1] = ld32(Bs_l + n * LDSS + c + 8);
        }
        #pragma unroll
        for (int mt = 0; mt < MT; mt++)
            #pragma unroll
            for (int nt = 0; nt < NT; nt++) {
                mma16816(acc[mt][nt], ah[mt], bh[nt]);
                mma16816(acc[mt][nt], ah[mt], bl[nt]);
                mma16816(acc[mt][nt], al[mt], bh[nt]);
            }
    }
}

// ---------------------------------------------------------------------------
// Weight transpose + split: W [K,N] fp32 -> Wt_hi/lo [N,K] bf16
// ---------------------------------------------------------------------------
__global__ __launch_bounds__(256)
void wsplit_t(const float* __restrict__ W, int K, int N,
              __nv_bfloat16* __restrict__ Whi, __nv_bfloat16* __restrict__ Wlo)
{
    __shared__ float sm[32][33];
    const int k0 = blockIdx.y * 32, n0 = blockIdx.x * 32;
    const int tid = threadIdx.x;

    for (int i = tid; i < 32 * 8; i += 256) {
        int r = i >> 3, c4 = i & 7;
        float4 v = *reinterpret_cast<const float4*>(&W[(size_t)(k0 + r) * N + n0 + c4 * 4]);
        sm[r][c4 * 4 + 0] = v.x; sm[r][c4 * 4 + 1] = v.y;
        sm[r][c4 * 4 + 2] = v.z; sm[r][c4 * 4 + 3] = v.w;
    }
    __syncthreads();
    for (int i = tid; i < 32 * 8; i += 256) {
        int n = i >> 3, k4 = i & 7;
        __align__(8) __nv_bfloat16 h[4], l[4];
        #pragma unroll
        for (int j = 0; j < 4; j++) {
            float v = sm[k4 * 4 + j][n];
            h[j] = __float2bfloat16(v);
            l[j] = __float2bfloat16(v - __bfloat162float(h[j]));
        }
        *reinterpret_cast<uint2*>(&Whi[(size_t)(n0 + n) * K + k0 + k4 * 4]) = *reinterpret_cast<uint2*>(h);
        *reinterpret_cast<uint2*>(&Wlo[(size_t)(n0 + n) * K + k0 + k4 * 4]) = *reinterpret_cast<uint2*>(l);
    }
}

// ---------------------------------------------------------------------------
// V transpose (bf16): V [b*S+s][h*D+d] -> Vt [(b*H+h)*D+d][s]
// ---------------------------------------------------------------------------
__global__ __launch_bounds__(256)
void vtrans(const __nv_bfloat16* __restrict__ Vh, const __nv_bfloat16* __restrict__ Vl,
            __nv_bfloat16* __restrict__ Vth, __nv_bfloat16* __restrict__ Vtl)
{
    __shared__ __nv_bfloat16 sm[64][72];
    const int z = blockIdx.z, bb = z >> 4, hh = z & 15;
    const int s0 = blockIdx.x * 64;

    #pragma unroll
    for (int p = 0; p < 2; p++) {
        const __nv_bfloat16* src = p ? Vl : Vh;
        __nv_bfloat16* dst = p ? Vtl : Vth;
        const __nv_bfloat16* sp = src + (size_t)(bb * S + s0) * EMB + hh * D;
        for (int i = threadIdx.x; i < 64 * 16; i += 256) {
            int s = i >> 4, d4 = i & 15;
            *reinterpret_cast<uint2*>(&sm[s][d4 * 4]) =
                *reinterpret_cast<const uint2*>(&sp[(size_t)s * EMB + d4 * 4]);
        }
        __syncthreads();
        __nv_bfloat16* dp = dst + (size_t)z * D * S + s0;
        for (int i = threadIdx.x; i < 64 * 16; i += 256) {
            int d = i >> 4, s4 = i & 15;
            __align__(8) __nv_bfloat16 t[4];
            t[0] = sm[s4 * 4 + 0][d]; t[1] = sm[s4 * 4 + 1][d];
            t[2] = sm[s4 * 4 + 2][d]; t[3] = sm[s4 * 4 + 3][d];
            *reinterpret_cast<uint2*>(&dp[(size_t)d * S + s4 * 4]) = *reinterpret_cast<uint2*>(t);
        }
        __syncthreads();
    }
}

// ---------------------------------------------------------------------------
// Projection GEMM (NT) — unchanged from R5
// ---------------------------------------------------------------------------
template <bool A_SPLIT, bool OUT_SPLIT>
__global__ __launch_bounds__(256)
void proj_nt(int K,
             const float* __restrict__ Af,
             const __nv_bfloat16* __restrict__ Ah, const __nv_bfloat16* __restrict__ Al,
             int lda,
             const __nv_bfloat16* __restrict__ Bth, const __nv_bfloat16* __restrict__ Btl,
             float* __restrict__ Cf,
             __nv_bfloat16* __restrict__ Ch, __nv_bfloat16* __restrict__ Cl,
             int ldc, const float* __restrict__ bias, float alpha)
{
    __shared__ __nv_bfloat16 Ash[128 * LDSS], Asl[128 * LDSS];
    __shared__ __nv_bfloat16 Bsh[128 * LDSS], Bsl[128 * LDSS];

    const int tid = threadIdx.x, lane = tid & 31, wid = tid >> 5;
    const int wm = wid >> 2, wn = wid & 3;
    const int row0 = blockIdx.y * 128, col0 = blockIdx.x * 128;

    float acc[4][4][4] = {};

    for (int k0 = 0; k0 < K; k0 += 32) {
        if (A_SPLIT) {
            stage_bf16<128, 256>(Ah + (size_t)row0 * lda + k0, lda, Ash, tid);
            stage_bf16<128, 256>(Al + (size_t)row0 * lda + k0, lda, Asl, tid);
        } else {
            stage_f32<128, 256>(Af + (size_t)row0 * lda + k0, lda, Ash, Asl, tid);
        }
        stage_bf16<128, 256>(Bth + (size_t)col0 * K + k0, K, Bsh, tid);
        stage_bf16<128, 256>(Btl + (size_t)col0 * K + k0, K, Bsl, tid);
        __syncthreads();
        mma_iter<4, 4>(Ash, Asl, Bsh, Bsl, wm * 64, wn * 32, lane, acc);
        __syncthreads();
    }

    #pragma unroll
    for (int mt = 0; mt < 4; mt++)
        #pragma unroll
        for (int nt = 0; nt < 4; nt++) {
            int r0 = row0 + wm * 64 + mt * 16 + (lane >> 2);
            int cc = col0 + wn * 32 + nt * 8 + ((lane & 3) << 1);
            float b0 = bias[cc], b1 = bias[cc + 1];
            #pragma unroll
            for (int half = 0; half < 2; half++) {
                int r = r0 + half * 8;
                float v0 = (acc[mt][nt][half * 2 + 0] + b0) * alpha;
                float v1 = (acc[mt][nt][half * 2 + 1] + b1) * alpha;
                if (OUT_SPLIT) {
                    uint32_t hi, lo;
                    split2(v0, v1, hi, lo);
                    *reinterpret_cast<uint32_t*>(&Ch[(size_t)r * ldc + cc]) = hi;
                    *reinterpret_cast<uint32_t*>(&Cl[(size_t)r * ldc + cc]) = lo;
                } else {
                    float2 o; o.x = v0; o.y = v1;
                    *reinterpret_cast<float2*>(&Cf[(size_t)r * ldc + cc]) = o;
                }
            }
        }
}

// ---------------------------------------------------------------------------
// Fused flash attention: scores + online softmax + PV, no P materialization.
// Grid: (T/128, B*H). 256 threads = 8 warps; warp w owns t-rows [w*16, w*16+16).
// Per s-tile of 128: S = Q K^T (split-bf16 3-MMA) + mask, online softmax in
// accumulator registers, P re-split hi/lo in registers, O += P V (3-MMA).
// ---------------------------------------------------------------------------
__global__ __launch_bounds__(256)
void flash_attn(const __nv_bfloat16* __restrict__ Qh, const __nv_bfloat16* __restrict__ Ql,
                const __nv_bfloat16* __restrict__ Kh, const __nv_bfloat16* __restrict__ Kl,
                const __nv_bfloat16* __restrict__ Vth, const __nv_bfloat16* __restrict__ Vtl,
                const float* __restrict__ mask, const float* __restrict__ head_mask,
                __nv_bfloat16* __restrict__ Ch, __nv_bfloat16* __restrict__ Cl)
{
    constexpr int LDK = 72;    // K tile [128 s][64 k] row stride (bank-conflict-free)
    constexpr int LDV = 136;   // V tile [64 d][128 s] row stride
    extern __shared__ __align__(16) char smraw[];
    __nv_bfloat16* Ksh = reinterpret_cast<__nv_bfloat16*>(smraw);     // 128*LDK
    __nv_bfloat16* Ksl = Ksh + 128 * LDK;
    __nv_bfloat16* Vsh = Ksl + 128 * LDK;                             // 64*LDV
    __nv_bfloat16* Vsl = Vsh + 64 * LDV;

    const int tid = threadIdx.x, lane = tid & 31, wid = tid >> 5;
    const int z = blockIdx.y, bb = z >> 4, hh = z & 15;
    const int row0 = blockIdx.x * 128;
    const int tr = row0 + wid * 16 + (lane >> 2);       // this lane's first t-row (local)

    // ---- Q fragments (register-resident for whole kernel), k = 0..63 ----
    uint32_t qfh[4][4], qfl[4][4];
    {
        const size_t qrow = (size_t)(bb * T + tr) * EMB + hh * D;
        #pragma unroll
        for (int ks = 0; ks < 4; ks++) {
            const int c = ks * 16 + (lane & 3) * 2;
            qfh[ks][0] = ld32(Qh + qrow + c);
            qfh[ks][1] = ld32(Qh + qrow + (size_t)8 * EMB + c);
            qfh[ks][2] = ld32(Qh + qrow + c + 8);
            qfh[ks][3] = ld32(Qh + qrow + (size_t)8 * EMB + c + 8);
            qfl[ks][0] = ld32(Ql + qrow + c);
            qfl[ks][1] = ld32(Ql + qrow + (size_t)8 * EMB + c);
            qfl[ks][2] = ld32(Ql + qrow + c + 8);
            qfl[ks][3] = ld32(Ql + qrow + (size_t)8 * EMB + c + 8);
        }
    }

    float oacc[8][4] = {};
    float mrun[2] = {-1e30f, -1e30f};
    float lrun[2] = {0.0f, 0.0f};

    const __nv_bfloat16* vbase_h = Vth + (size_t)z * D * S;
    const __nv_bfloat16* vbase_l = Vtl + (size_t)z * D * S;
    const float* Mz = mask + (size_t)bb * T * S;

    for (int s0 = 0; s0 < S; s0 += 128) {
        // ---- stage K tile [128][64] hi/lo, V tile [64][128] hi/lo ----
        {
            const __nv_bfloat16* kh = Kh + (size_t)(bb * S + s0) * EMB + hh * D;
            const __nv_bfloat16* kl = Kl + (size_t)(bb * S + s0) * EMB + hh * D;
            #pragma unroll
            for (int i = tid; i < 1024; i += 256) {
                int r = i >> 3, c8 = (i & 7) * 8;
                *reinterpret_cast<uint4*>(&Ksh[r * LDK + c8]) =
                    *reinterpret_cast<const uint4*>(&kh[(size_t)r * EMB + c8]);
                *reinterpret_cast<uint4*>(&Ksl[r * LDK + c8]) =
                    *reinterpret_cast<const uint4*>(&kl[(size_t)r * EMB + c8]);
            }
            #pragma unroll
            for (int i = tid; i < 1024; i += 256) {
                int r = i >> 4, c8 = (i & 15) * 8;
                *reinterpret_cast<uint4*>(&Vsh[r * LDV + c8]) =
                    *reinterpret_cast<const uint4*>(&vbase_h[(size_t)r * S + s0 + c8]);
                *reinterpret_cast<uint4*>(&Vsl[r * LDV + c8]) =
                    *reinterpret_cast<const uint4*>(&vbase_l[(size_t)r * S + s0 + c8]);
            }
        }
        __syncthreads();

        // ---- scores: S tile 16(t) x 128(s) per warp ----
        float sacc[16][4] = {};
        #pragma unroll
        for (int ks = 0; ks < 4; ks++) {
            #pragma unroll
            for (int nt = 0; nt < 16; nt++) {
                const int n = nt * 8 + (lane >> 2);
                const int c = ks * 16 + (lane & 3) * 2;
                uint32_t bh[2], bl[2];
                bh[0] = ld32(&Ksh[n * LDK + c]); bh[1] = ld32(&Ksh[n * LDK + c + 8]);
                bl[0] = ld32(&Ksl[n * LDK + c]); bl[1] = ld32(&Ksl[n * LDK + c + 8]);
                mma16816(sacc[nt], qfh[ks], bh);
                mma16816(sacc[nt], qfh[ks], bl);
                mma16816(sacc[nt], qfl[ks], bh);
            }
        }

        // ---- + mask ----
        #pragma unroll
        for (int nt = 0; nt < 16; nt++) {
            const int cg = s0 + nt * 8 + (lane & 3) * 2;
            float2 m0 = *reinterpret_cast<const float2*>(&Mz[(size_t)tr * S + cg]);
            float2 m1 = *reinterpret_cast<const float2*>(&Mz[(size_t)(tr + 8) * S + cg]);
            sacc[nt][0] += m0.x; sacc[nt][1] += m0.y;
            sacc[nt][2] += m1.x; sacc[nt][3] += m1.y;
        }

        // ---- online softmax (per row-half: rows tr and tr+8) ----
        #pragma unroll
        for (int hf = 0; hf < 2; hf++) {
            float vm = -1e30f;
            #pragma unroll
            for (int nt = 0; nt < 16; nt++)
                vm = fmaxf(vm, fmaxf(sacc[nt][hf * 2], sacc[nt][hf * 2 + 1]));
            vm = fmaxf(vm, __shfl_xor_sync(0xffffffffu, vm, 1));
            vm = fmaxf(vm, __shfl_xor_sync(0xffffffffu, vm, 2));
            const float mnew = fmaxf(mrun[hf], vm);
            const float f = __expf(mrun[hf] - mnew);
            mrun[hf] = mnew;
            lrun[hf] *= f;
            #pragma unroll
            for (int nt = 0; nt < 8; nt++) {
                oacc[nt][hf * 2 + 0] *= f;
                oacc[nt][hf * 2 + 1] *= f;
            }
            float ls = 0.0f;
            #pragma unroll
            for (int nt = 0; nt < 16; nt++) {
                float e0 = __expf(sacc[nt][hf * 2 + 0] - mnew);
                float e1 = __expf(sacc[nt][hf * 2 + 1] - mnew);
                sacc[nt][hf * 2 + 0] = e0;
                sacc[nt][hf * 2 + 1] = e1;
                ls += e0 + e1;
            }
            lrun[hf] += ls;
        }

        // ---- PV: O(16t x 64d) += P(16t x 128s) @ V^T(64d x 128s)^T ----
        // Score-acc fragment layout == A-operand fragment layout: re-split in regs.
        #pragma unroll
        for (int ks = 0; ks < 8; ks++) {
            uint32_t ph[4], pl[4];
            split2(sacc[2 * ks][0],     sacc[2 * ks][1],     ph[0], pl[0]);
            split2(sacc[2 * ks][2],     sacc[2 * ks][3],     ph[1], pl[1]);
            split2(sacc[2 * ks + 1][0], sacc[2 * ks + 1][1], ph[2], pl[2]);
            split2(sacc[2 * ks + 1][2], sacc[2 * ks + 1][3], ph[3], pl[3]);
            #pragma unroll
            for (int nt = 0; nt < 8; nt++) {
                const int n = nt * 8 + (lane >> 2);
                const int c = ks * 16 + (lane & 3) * 2;
                uint32_t bh[2], bl[2];
                bh[0] = ld32(&Vsh[n * LDV + c]); bh[1] = ld32(&Vsh[n * LDV + c + 8]);
                bl[0] = ld32(&Vsl[n * LDV + c]); bl[1] = ld32(&Vsl[n * LDV + c + 8]);
                mma16816(oacc[nt], ph, bh);
                mma16816(oacc[nt], ph, bl);
                mma16816(oacc[nt], pl, bh);
            }
        }
        __syncthreads();
    }

    // ---- epilogue: normalize, head-mask scale, split to ctx hi/lo ----
    float scale[2];
    #pragma unroll
    for (int hf = 0; hf < 2; hf++) {
        float l = lrun[hf];
        l += __shfl_xor_sync(0xffffffffu, l, 1);
        l += __shfl_xor_sync(0xffffffffu, l, 2);
        scale[hf] = head_mask[hh] / l;
    }
    #pragma unroll
    for (int nt = 0; nt < 8; nt++) {
        const int cc = hh * D + nt * 8 + (lane & 3) * 2;
        #pragma unroll
        for (int hf = 0; hf < 2; hf++) {
            const size_t r = (size_t)(bb * T + tr + hf * 8);
            uint32_t hi, lo;
            split2(oacc[nt][hf * 2 + 0] * scale[hf],
                   oacc[nt][hf * 2 + 1] * scale[hf], hi, lo);
            *reinterpret_cast<uint32_t*>(&Ch[r * EMB + cc]) = hi;
            *reinterpret_cast<uint32_t*>(&Cl[r * EMB + cc]) = lo;
        }
    }
}

static constexpr int FLASH_SMEM = (2 * 128 * 72 + 2 * 64 * 136) * (int)sizeof(__nv_bfloat16);

// ---------------------------------------------------------------------------
extern "C" void kernel_launch(void* const* d_in, const int* in_sizes, int n_in,
                              void* d_out, int out_size)
{
    const float* hs   = (const float*)d_in[0];
    const float* kv   = (const float*)d_in[1];
    const float* mask = (const float*)d_in[2];
    const float* hm   = (const float*)d_in[3];
    const float* Wq   = (const float*)d_in[4];
    const float* bq   = (const float*)d_in[5];
    const float* Wk   = (const float*)d_in[6];
    const float* bk   = (const float*)d_in[7];
    const float* Wv   = (const float*)d_in[8];
    const float* bv   = (const float*)d_in[9];
    const float* Wo   = (const float*)d_in[10];
    const float* bo   = (const float*)d_in[11];
    float* out = (float*)d_out;

    __nv_bfloat16 *Qh, *Ql, *Kh, *Kl, *Vh, *Vl, *Vth, *Vtl, *Ch, *Cl;
    __nv_bfloat16 *Wqh, *Wql, *Wkh, *Wkl, *Wvh, *Wvl, *Woh, *Wol;
    cudaGetSymbolAddress((void**)&Qh, g_Qhi);  cudaGetSymbolAddress((void**)&Ql, g_Qlo);
    cudaGetSymbolAddress((void**)&Kh, g_Khi);  cudaGetSymbolAddress((void**)&Kl, g_Klo);
    cudaGetSymbolAddress((void**)&Vh, g_Vhi);  cudaGetSymbolAddress((void**)&Vl, g_Vlo);
    cudaGetSymbolAddress((void**)&Vth, g_Vthi); cudaGetSymbolAddress((void**)&Vtl, g_Vtlo);
    cudaGetSymbolAddress((void**)&Ch, g_Chi);  cudaGetSymbolAddress((void**)&Cl, g_Clo);
    cudaGetSymbolAddress((void**)&Wqh, g_Wqthi); cudaGetSymbolAddress((void**)&Wql, g_Wqtlo);
    cudaGetSymbolAddress((void**)&Wkh, g_Wkthi); cudaGetSymbolAddress((void**)&Wkl, g_Wktlo);
    cudaGetSymbolAddress((void**)&Wvh, g_Wvthi); cudaGetSymbolAddress((void**)&Wvl, g_Wvtlo);
    cudaGetSymbolAddress((void**)&Woh, g_Wothi); cudaGetSymbolAddress((void**)&Wol, g_Wotlo);

    cudaFuncSetAttribute(flash_attn, cudaFuncAttributeMaxDynamicSharedMemorySize, FLASH_SMEM);

    // Weight transpose + split
    wsplit_t<<<dim3(EMB / 32, QIN / 32), 256>>>(Wq, QIN, EMB, Wqh, Wql);
    wsplit_t<<<dim3(EMB / 32, KVIN / 32), 256>>>(Wk, KVIN, EMB, Wkh, Wkl);
    wsplit_t<<<dim3(EMB / 32, KVIN / 32), 256>>>(Wv, KVIN, EMB, Wvh, Wvl);
    wsplit_t<<<dim3(EMB / 32, EMB / 32), 256>>>(Wo, EMB, EMB, Woh, Wol);

    // Projections -> split bf16
    proj_nt<false, true><<<dim3(EMB / 128, (B * T) / 128), 256>>>(
        QIN, hs, nullptr, nullptr, QIN, Wqh, Wql,
        nullptr, Qh, Ql, EMB, bq, SCALING);
    proj_nt<false, true><<<dim3(EMB / 128, (B * S) / 128), 256>>>(
        KVIN, kv, nullptr, nullptr, KVIN, Wkh, Wkl,
        nullptr, Kh, Kl, EMB, bk, 1.0f);
    proj_nt<false, true><<<dim3(EMB / 128, (B * S) / 128), 256>>>(
        KVIN, kv, nullptr, nullptr, KVIN, Wvh, Wvl,
        nullptr, Vh, Vl, EMB, bv, 1.0f);

    // V transpose per head
    vtrans<<<dim3(S / 64, 1, B * H), 256>>>(Vh, Vl, Vth, Vtl);

    // Fused scores + softmax + PV
    flash_attn<<<dim3(T / 128, B * H), 256, FLASH_SMEM>>>(
        Qh, Ql, Kh, Kl, Vth, Vtl, mask, hm, Ch, Cl);

    // out = ctx @ Wo + bo
    proj_nt<true, false><<<dim3(EMB / 128, (B * T) / 128), 256>>>(
        EMB, nullptr, Ch, Cl, EMB, Woh, Wol,
        out, nullptr, nullptr, EMB, bo, 1.0f);
}

// round 8
// speedup vs baseline: 2.5857x; 1.2042x over previous
#include <cuda_runtime.h>
#include <cuda_bf16.h>
#include <cstdint>

// Problem constants
static constexpr int B   = 8;
static constexpr int T   = 1024;
static constexpr int S   = 1024;
static constexpr int H   = 16;
static constexpr int D   = 64;
static constexpr int EMB = 1024;
static constexpr int QIN = 1024;
static constexpr int KVIN = 256;
static constexpr float SCALING = 0.125f;

// ---------------------------------------------------------------------------
// Scratch (__device__ globals; allocation-free rule)
// ---------------------------------------------------------------------------
__device__ __nv_bfloat16 g_HShi[B * T * QIN],  g_HSlo[B * T * QIN];      // split hs
__device__ __nv_bfloat16 g_KVhi[B * S * KVIN], g_KVlo[B * S * KVIN];     // split kv

__device__ __nv_bfloat16 g_Qhi[B * T * EMB], g_Qlo[B * T * EMB];
__device__ __nv_bfloat16 g_Khi[B * S * EMB], g_Klo[B * S * EMB];
__device__ __nv_bfloat16 g_Vhi[B * S * EMB], g_Vlo[B * S * EMB];
__device__ __nv_bfloat16 g_Vthi[B * H * D * S], g_Vtlo[B * H * D * S];   // [z*D+d][S]
__device__ __nv_bfloat16 g_Chi[B * T * EMB], g_Clo[B * T * EMB];         // ctx

__device__ __nv_bfloat16 g_Wqthi[EMB * QIN],  g_Wqtlo[EMB * QIN];        // [N][K]
__device__ __nv_bfloat16 g_Wkthi[EMB * KVIN], g_Wktlo[EMB * KVIN];
__device__ __nv_bfloat16 g_Wvthi[EMB * KVIN], g_Wvtlo[EMB * KVIN];
__device__ __nv_bfloat16 g_Wothi[EMB * EMB],  g_Wotlo[EMB * EMB];

// ---------------------------------------------------------------------------
// Low-level helpers
// ---------------------------------------------------------------------------
static constexpr int LDSS = 40;   // smem row stride (bf16) for 32-col proj tiles

__device__ __forceinline__ uint32_t ld32(const __nv_bfloat16* p) {
    return *reinterpret_cast<const uint32_t*>(p);
}

__device__ __forceinline__ uint32_t s2u(const void* p) {
    return (uint32_t)__cvta_generic_to_shared(p);
}

__device__ __forceinline__ void cpa16(uint32_t dst, const void* src) {
    asm volatile("cp.async.cg.shared.global [%0], [%1], 16;\n" :: "r"(dst), "l"(src));
}
__device__ __forceinline__ void cpcommit() {
    asm volatile("cp.async.commit_group;\n");
}
template <int N> __device__ __forceinline__ void cpwait() {
    asm volatile("cp.async.wait_group %0;\n" :: "n"(N));
}

__device__ __forceinline__ void ldsm4(uint32_t* r, uint32_t a) {
    asm volatile("ldmatrix.sync.aligned.m8n8.x4.shared.b16 {%0,%1,%2,%3}, [%4];\n"
                 : "=r"(r[0]), "=r"(r[1]), "=r"(r[2]), "=r"(r[3]) : "r"(a));
}

__device__ __forceinline__ void mma16816(float* c, const uint32_t* a, const uint32_t* b) {
    asm volatile(
        "mma.sync.aligned.m16n8k16.row.col.f32.bf16.bf16.f32 "
        "{%0,%1,%2,%3}, {%4,%5,%6,%7}, {%8,%9}, {%0,%1,%2,%3};\n"
        : "+f"(c[0]), "+f"(c[1]), "+f"(c[2]), "+f"(c[3])
        : "r"(a[0]), "r"(a[1]), "r"(a[2]), "r"(a[3]), "r"(b[0]), "r"(b[1]));
}

__device__ __forceinline__ void split2(float v0, float v1, uint32_t& hi, uint32_t& lo) {
    __nv_bfloat16 h0 = __float2bfloat16(v0), h1 = __float2bfloat16(v1);
    __nv_bfloat16 l0 = __float2bfloat16(v0 - __bfloat162float(h0));
    __nv_bfloat16 l1 = __float2bfloat16(v1 - __bfloat162float(h1));
    __nv_bfloat162 hp; hp.x = h0; hp.y = h1;
    __nv_bfloat162 lp; lp.x = l0; lp.y = l1;
    hi = *reinterpret_cast<uint32_t*>(&hp);
    lo = *reinterpret_cast<uint32_t*>(&lp);
}

// ---------------------------------------------------------------------------
// Activation split: fp32 -> bf16 hi/lo (elementwise, vectorized)
// ---------------------------------------------------------------------------
__global__ __launch_bounds__(256)
void split_act(const float* __restrict__ x,
               __nv_bfloat16* __restrict__ xh, __nv_bfloat16* __restrict__ xl, int n4)
{
    int i = blockIdx.x * 256 + threadIdx.x;
    if (i >= n4) return;
    float4 v = reinterpret_cast<const float4*>(x)[i];
    float vv[4] = {v.x, v.y, v.z, v.w};
    __align__(8) __nv_bfloat16 h[4], l[4];
    #pragma unroll
    for (int j = 0; j < 4; j++) {
        h[j] = __float2bfloat16(vv[j]);
        l[j] = __float2bfloat16(vv[j] - __bfloat162float(h[j]));
    }
    reinterpret_cast<uint2*>(xh)[i] = *reinterpret_cast<uint2*>(h);
    reinterpret_cast<uint2*>(xl)[i] = *reinterpret_cast<uint2*>(l);
}

// ---------------------------------------------------------------------------
// Weight transpose + split: W [K,N] fp32 -> Wt_hi/lo [N,K] bf16
// ---------------------------------------------------------------------------
__global__ __launch_bounds__(256)
void wsplit_t(const float* __restrict__ W, int K, int N,
              __nv_bfloat16* __restrict__ Whi, __nv_bfloat16* __restrict__ Wlo)
{
    __shared__ float sm[32][33];
    const int k0 = blockIdx.y * 32, n0 = blockIdx.x * 32;
    const int tid = threadIdx.x;

    for (int i = tid; i < 32 * 8; i += 256) {
        int r = i >> 3, c4 = i & 7;
        float4 v = *reinterpret_cast<const float4*>(&W[(size_t)(k0 + r) * N + n0 + c4 * 4]);
        sm[r][c4 * 4 + 0] = v.x; sm[r][c4 * 4 + 1] = v.y;
        sm[r][c4 * 4 + 2] = v.z; sm[r][c4 * 4 + 3] = v.w;
    }
    __syncthreads();
    for (int i = tid; i < 32 * 8; i += 256) {
        int n = i >> 3, k4 = i & 7;
        __align__(8) __nv_bfloat16 h[4], l[4];
        #pragma unroll
        for (int j = 0; j < 4; j++) {
            float v = sm[k4 * 4 + j][n];
            h[j] = __float2bfloat16(v);
            l[j] = __float2bfloat16(v - __bfloat162float(h[j]));
        }
        *reinterpret_cast<uint2*>(&Whi[(size_t)(n0 + n) * K + k0 + k4 * 4]) = *reinterpret_cast<uint2*>(h);
        *reinterpret_cast<uint2*>(&Wlo[(size_t)(n0 + n) * K + k0 + k4 * 4]) = *reinterpret_cast<uint2*>(l);
    }
}

// ---------------------------------------------------------------------------
// V transpose (bf16): V [b*S+s][h*D+d] -> Vt [(b*H+h)*D+d][s]
// ---------------------------------------------------------------------------
__global__ __launch_bounds__(256)
void vtrans(const __nv_bfloat16* __restrict__ Vh, const __nv_bfloat16* __restrict__ Vl,
            __nv_bfloat16* __restrict__ Vth, __nv_bfloat16* __restrict__ Vtl)
{
    __shared__ __nv_bfloat16 sm[64][72];
    const int z = blockIdx.z, bb = z >> 4, hh = z & 15;
    const int s0 = blockIdx.x * 64;

    #pragma unroll
    for (int p = 0; p < 2; p++) {
        const __nv_bfloat16* src = p ? Vl : Vh;
        __nv_bfloat16* dst = p ? Vtl : Vth;
        const __nv_bfloat16* sp = src + (size_t)(bb * S + s0) * EMB + hh * D;
        for (int i = threadIdx.x; i < 64 * 16; i += 256) {
            int s = i >> 4, d4 = i & 15;
            *reinterpret_cast<uint2*>(&sm[s][d4 * 4]) =
                *reinterpret_cast<const uint2*>(&sp[(size_t)s * EMB + d4 * 4]);
        }
        __syncthreads();
        __nv_bfloat16* dp = dst + (size_t)z * D * S + s0;
        for (int i = threadIdx.x; i < 64 * 16; i += 256) {
            int d = i >> 4, s4 = i & 15;
            __align__(8) __nv_bfloat16 t[4];
            t[0] = sm[s4 * 4 + 0][d]; t[1] = sm[s4 * 4 + 1][d];
            t[2] = sm[s4 * 4 + 2][d]; t[3] = sm[s4 * 4 + 3][d];
            *reinterpret_cast<uint2*>(&dp[(size_t)d * S + s4 * 4]) = *reinterpret_cast<uint2*>(t);
        }
        __syncthreads();
    }
}

// ---------------------------------------------------------------------------
// Projection GEMM (NT), split-bf16 3-MMA, cp.async 2-stage pipeline + ldmatrix.
// C[M,N] = (A[M,K] @ Bt[N,K]^T + bias) * alpha
// BM=BN=128, BK=32, 256 threads (8 warps 2x4), warp tile 64x32.
// Dynamic smem: 2 stages x 4 tiles x 128*LDSS bf16 = 81920 B.
// ---------------------------------------------------------------------------
template <bool OUT_SPLIT>
__global__ __launch_bounds__(256)
void proj_nt(int K,
             const __nv_bfloat16* __restrict__ Ah, const __nv_bfloat16* __restrict__ Al,
             int lda,
             const __nv_bfloat16* __restrict__ Bth, const __nv_bfloat16* __restrict__ Btl,
             float* __restrict__ Cf,
             __nv_bfloat16* __restrict__ Ch, __nv_bfloat16* __restrict__ Cl,
             int ldc, const float* __restrict__ bias, float alpha)
{
    constexpr int TILE = 128 * LDSS;
    extern __shared__ __nv_bfloat16 smp[];   // [2][4][TILE]

    const int tid = threadIdx.x, lane = tid & 31, wid = tid >> 5;
    const int wm = wid >> 2, wn = wid & 3;
    const int row0 = blockIdx.y * 128, col0 = blockIdx.x * 128;

    const __nv_bfloat16* aH = Ah + (size_t)row0 * lda;
    const __nv_bfloat16* aL = Al + (size_t)row0 * lda;
    const __nv_bfloat16* bH = Bth + (size_t)col0 * K;
    const __nv_bfloat16* bL = Btl + (size_t)col0 * K;

    const int g = lane >> 3, li = lane & 7;
    const int ar = ((g & 1) * 8) + li, ac = (g >> 1) * 8;   // A-frag ldmatrix lane map
    const int br = ((g >> 1) * 8) + li, bc = (g & 1) * 8;   // B-frag ldmatrix lane map

    float acc[4][4][4] = {};

    auto stage = [&](int st, int k0) {
        __nv_bfloat16* d = smp + st * 4 * TILE;
        #pragma unroll
        for (int i = tid; i < 512; i += 256) {
            int r = i >> 2, c = (i & 3) * 8;
            cpa16(s2u(d + 0 * TILE + r * LDSS + c), aH + (size_t)r * lda + k0 + c);
            cpa16(s2u(d + 1 * TILE + r * LDSS + c), aL + (size_t)r * lda + k0 + c);
            cpa16(s2u(d + 2 * TILE + r * LDSS + c), bH + (size_t)r * K + k0 + c);
            cpa16(s2u(d + 3 * TILE + r * LDSS + c), bL + (size_t)r * K + k0 + c);
        }
    };

    auto compute = [&](int st) {
        const __nv_bfloat16* Ash = smp + st * 4 * TILE;
        const __nv_bfloat16* Asl = Ash + TILE;
        const __nv_bfloat16* Bsh = Asl + TILE;
        const __nv_bfloat16* Bsl = Bsh + TILE;
        #pragma unroll
        for (int ks = 0; ks < 2; ks++) {
            const int c = ks * 16;
            uint32_t ah[4][4], al[4][4], bh[2][4], bl[2][4];
            #pragma unroll
            for (int mt = 0; mt < 4; mt++) {
                int r = wm * 64 + mt * 16 + ar;
                ldsm4(ah[mt], s2u(Ash + r * LDSS + c + ac));
                ldsm4(al[mt], s2u(Asl + r * LDSS + c + ac));
            }
            #pragma unroll
            for (int np = 0; np < 2; np++) {
                int n = wn * 32 + np * 16 + br;
                ldsm4(bh[np], s2u(Bsh + n * LDSS + c + bc));
                ldsm4(bl[np], s2u(Bsl + n * LDSS + c + bc));
            }
            #pragma unroll
            for (int mt = 0; mt < 4; mt++)
                #pragma unroll
                for (int nt = 0; nt < 4; nt++) {
                    const uint32_t* bph = &bh[nt >> 1][(nt & 1) * 2];
                    const uint32_t* bpl = &bl[nt >> 1][(nt & 1) * 2];
                    mma16816(acc[mt][nt], ah[mt], bph);
                    mma16816(acc[mt][nt], ah[mt], bpl);
                    mma16816(acc[mt][nt], al[mt], bph);
                }
        }
    };

    const int nit = K / 32;
    stage(0, 0);
    cpcommit();
    for (int it = 0; it < nit; it++) {
        if (it + 1 < nit) { stage((it + 1) & 1, (it + 1) * 32); cpcommit(); }
        if (it + 1 < nit) cpwait<1>(); else cpwait<0>();
        __syncthreads();
        compute(it & 1);
        __syncthreads();
    }

    #pragma unroll
    for (int mt = 0; mt < 4; mt++)
        #pragma unroll
        for (int nt = 0; nt < 4; nt++) {
            int r0 = row0 + wm * 64 + mt * 16 + (lane >> 2);
            int cc = col0 + wn * 32 + nt * 8 + ((lane & 3) << 1);
            float b0 = bias[cc], b1 = bias[cc + 1];
            #pragma unroll
            for (int half = 0; half < 2; half++) {
                int r = r0 + half * 8;
                float v0 = (acc[mt][nt][half * 2 + 0] + b0) * alpha;
                float v1 = (acc[mt][nt][half * 2 + 1] + b1) * alpha;
                if (OUT_SPLIT) {
                    uint32_t hi, lo;
                    split2(v0, v1, hi, lo);
                    *reinterpret_cast<uint32_t*>(&Ch[(size_t)r * ldc + cc]) = hi;
                    *reinterpret_cast<uint32_t*>(&Cl[(size_t)r * ldc + cc]) = lo;
                } else {
                    float2 o; o.x = v0; o.y = v1;
                    *reinterpret_cast<float2*>(&Cf[(size_t)r * ldc + cc]) = o;
                }
            }
        }
}

static constexpr int PROJ_SMEM = 2 * 4 * 128 * LDSS * (int)sizeof(__nv_bfloat16);  // 81920

// ---------------------------------------------------------------------------
// Fused flash attention with cp.async double-buffered K/V tiles + ldmatrix.
// Grid: (T/128, B*H). 256 threads = 8 warps; warp w owns t-rows [w*16, w*16+16).
// ---------------------------------------------------------------------------
static constexpr int LDK = 72;    // K tile [128 s][64 k] row stride
static constexpr int LDV = 136;   // V tile [64 d][128 s] row stride
static constexpr int KTILE = 128 * LDK;
static constexpr int VTILE = 64 * LDV;
static constexpr int FSTAGE = 2 * KTILE + 2 * VTILE;   // elems per stage
static constexpr int FLASH_SMEM = 2 * FSTAGE * (int)sizeof(__nv_bfloat16);  // 143360

__global__ __launch_bounds__(256)
void flash_attn(const __nv_bfloat16* __restrict__ Qh, const __nv_bfloat16* __restrict__ Ql,
                const __nv_bfloat16* __restrict__ Kh, const __nv_bfloat16* __restrict__ Kl,
                const __nv_bfloat16* __restrict__ Vth, const __nv_bfloat16* __restrict__ Vtl,
                const float* __restrict__ mask, const float* __restrict__ head_mask,
                __nv_bfloat16* __restrict__ Ch, __nv_bfloat16* __restrict__ Cl)
{
    extern __shared__ __nv_bfloat16 smf[];   // [2][FSTAGE]

    const int tid = threadIdx.x, lane = tid & 31, wid = tid >> 5;
    const int z = blockIdx.y, bb = z >> 4, hh = z & 15;
    const int row0 = blockIdx.x * 128;
    const int tr = row0 + wid * 16 + (lane >> 2);

    const int g = lane >> 3, li = lane & 7;
    const int br = ((g >> 1) * 8) + li, bc = (g & 1) * 8;   // B-frag ldmatrix lane map

    // ---- Q fragments (register-resident for whole kernel), k = 0..63 ----
    uint32_t qfh[4][4], qfl[4][4];
    {
        const size_t qrow = (size_t)(bb * T + tr) * EMB + hh * D;
        #pragma unroll
        for (int ks = 0; ks < 4; ks++) {
            const int c = ks * 16 + (lane & 3) * 2;
            qfh[ks][0] = ld32(Qh + qrow + c);
            qfh[ks][1] = ld32(Qh + qrow + (size_t)8 * EMB + c);
            qfh[ks][2] = ld32(Qh + qrow + c + 8);
            qfh[ks][3] = ld32(Qh + qrow + (size_t)8 * EMB + c + 8);
            qfl[ks][0] = ld32(Ql + qrow + c);
            qfl[ks][1] = ld32(Ql + qrow + (size_t)8 * EMB + c);
            qfl[ks][2] = ld32(Ql + qrow + c + 8);
            qfl[ks][3] = ld32(Ql + qrow + (size_t)8 * EMB + c + 8);
        }
    }

    float oacc[8][4] = {};
    float mrun[2] = {-1e30f, -1e30f};
    float lrun[2] = {0.0f, 0.0f};

    const __nv_bfloat16* kbase_h = Kh + (size_t)bb * S * EMB + hh * D;
    const __nv_bfloat16* kbase_l = Kl + (size_t)bb * S * EMB + hh * D;
    const __nv_bfloat16* vbase_h = Vth + (size_t)z * D * S;
    const __nv_bfloat16* vbase_l = Vtl + (size_t)z * D * S;
    const float* Mz = mask + (size_t)bb * T * S;

    auto stageKV = [&](int st, int s0) {
        __nv_bfloat16* kd  = smf + st * FSTAGE;
        __nv_bfloat16* kdl = kd + KTILE;
        __nv_bfloat16* vd  = kdl + KTILE;
        __nv_bfloat16* vdl = vd + VTILE;
        #pragma unroll
        for (int i = tid; i < 1024; i += 256) {
            int r = i >> 3, c = (i & 7) * 8;
            cpa16(s2u(kd  + r * LDK + c), kbase_h + (size_t)(s0 + r) * EMB + c);
            cpa16(s2u(kdl + r * LDK + c), kbase_l + (size_t)(s0 + r) * EMB + c);
        }
        #pragma unroll
        for (int i = tid; i < 1024; i += 256) {
            int r = i >> 4, c = (i & 15) * 8;
            cpa16(s2u(vd  + r * LDV + c), vbase_h + (size_t)r * S + s0 + c);
            cpa16(s2u(vdl + r * LDV + c), vbase_l + (size_t)r * S + s0 + c);
        }
    };

    stageKV(0, 0);
    cpcommit();

    constexpr int NS = S / 128;
    for (int is = 0; is < NS; is++) {
        if (is + 1 < NS) { stageKV((is + 1) & 1, (is + 1) * 128); cpcommit(); }
        if (is + 1 < NS) cpwait<1>(); else cpwait<0>();
        __syncthreads();

        const int s0 = is * 128;
        const __nv_bfloat16* Ksh = smf + (is & 1) * FSTAGE;
        const __nv_bfloat16* Ksl = Ksh + KTILE;
        const __nv_bfloat16* Vsh = Ksl + KTILE;
        const __nv_bfloat16* Vsl = Vsh + VTILE;

        // ---- scores: S tile 16(t) x 128(s) per warp ----
        float sacc[16][4] = {};
        #pragma unroll
        for (int ks = 0; ks < 4; ks++) {
            const int c = ks * 16;
            #pragma unroll
            for (int np = 0; np < 8; np++) {
                const int n = np * 16 + br;
                uint32_t kbh[4], kbl[4];
                ldsm4(kbh, s2u(Ksh + n * LDK + c + bc));
                ldsm4(kbl, s2u(Ksl + n * LDK + c + bc));
                mma16816(sacc[2 * np],     qfh[ks], kbh);
                mma16816(sacc[2 * np],     qfh[ks], kbl);
                mma16816(sacc[2 * np],     qfl[ks], kbh);
                mma16816(sacc[2 * np + 1], qfh[ks], kbh + 2);
                mma16816(sacc[2 * np + 1], qfh[ks], kbl + 2);
                mma16816(sacc[2 * np + 1], qfl[ks], kbh + 2);
            }
        }

        // ---- + mask ----
        #pragma unroll
        for (int nt = 0; nt < 16; nt++) {
            const int cg = s0 + nt * 8 + (lane & 3) * 2;
            float2 m0 = *reinterpret_cast<const float2*>(&Mz[(size_t)tr * S + cg]);
            float2 m1 = *reinterpret_cast<const float2*>(&Mz[(size_t)(tr + 8) * S + cg]);
            sacc[nt][0] += m0.x; sacc[nt][1] += m0.y;
            sacc[nt][2] += m1.x; sacc[nt][3] += m1.y;
        }

        // ---- online softmax (per row-half: rows tr and tr+8) ----
        #pragma unroll
        for (int hf = 0; hf < 2; hf++) {
            float vm = -1e30f;
            #pragma unroll
            for (int nt = 0; nt < 16; nt++)
                vm = fmaxf(vm, fmaxf(sacc[nt][hf * 2], sacc[nt][hf * 2 + 1]));
            vm = fmaxf(vm, __shfl_xor_sync(0xffffffffu, vm, 1));
            vm = fmaxf(vm, __shfl_xor_sync(0xffffffffu, vm, 2));
            const float mnew = fmaxf(mrun[hf], vm);
            const float f = __expf(mrun[hf] - mnew);
            mrun[hf] = mnew;
            lrun[hf] *= f;
            #pragma unroll
            for (int nt = 0; nt < 8; nt++) {
                oacc[nt][hf * 2 + 0] *= f;
                oacc[nt][hf * 2 + 1] *= f;
            }
            float ls = 0.0f;
            #pragma unroll
            for (int nt = 0; nt < 16; nt++) {
                float e0 = __expf(sacc[nt][hf * 2 + 0] - mnew);
                float e1 = __expf(sacc[nt][hf * 2 + 1] - mnew);
                sacc[nt][hf * 2 + 0] = e0;
                sacc[nt][hf * 2 + 1] = e1;
                ls += e0 + e1;
            }
            lrun[hf] += ls;
        }

        // ---- PV: O(16t x 64d) += P(16t x 128s) @ Vt(64d x 128s)^T ----
        #pragma unroll
        for (int ks = 0; ks < 8; ks++) {
            uint32_t ph[4], pl[4];
            split2(sacc[2 * ks][0],     sacc[2 * ks][1],     ph[0], pl[0]);
            split2(sacc[2 * ks][2],     sacc[2 * ks][3],     ph[1], pl[1]);
            split2(sacc[2 * ks + 1][0], sacc[2 * ks + 1][1], ph[2], pl[2]);
            split2(sacc[2 * ks + 1][2], sacc[2 * ks + 1][3], ph[3], pl[3]);
            const int c = ks * 16;
            #pragma unroll
            for (int np = 0; np < 4; np++) {
                const int n = np * 16 + br;
                uint32_t vbh[4], vbl[4];
                ldsm4(vbh, s2u(Vsh + n * LDV + c + bc));
                ldsm4(vbl, s2u(Vsl + n * LDV + c + bc));
                mma16816(oacc[2 * np],     ph, vbh);
                mma16816(oacc[2 * np],     ph, vbl);
                mma16816(oacc[2 * np],     pl, vbh);
                mma16816(oacc[2 * np + 1], ph, vbh + 2);
                mma16816(oacc[2 * np + 1], ph, vbl + 2);
                mma16816(oacc[2 * np + 1], pl, vbh + 2);
            }
        }
        __syncthreads();
    }

    // ---- epilogue: normalize, head-mask scale, split to ctx hi/lo ----
    float scale[2];
    #pragma unroll
    for (int hf = 0; hf < 2; hf++) {
        float l = lrun[hf];
        l += __shfl_xor_sync(0xffffffffu, l, 1);
        l += __shfl_xor_sync(0xffffffffu, l, 2);
        scale[hf] = head_mask[hh] / l;
    }
    #pragma unroll
    for (int nt = 0; nt < 8; nt++) {
        const int cc = hh * D + nt * 8 + (lane & 3) * 2;
        #pragma unroll
        for (int hf = 0; hf < 2; hf++) {
            const size_t r = (size_t)(bb * T + tr + hf * 8);
            uint32_t hi, lo;
            split2(oacc[nt][hf * 2 + 0] * scale[hf],
                   oacc[nt][hf * 2 + 1] * scale[hf], hi, lo);
            *reinterpret_cast<uint32_t*>(&Ch[r * EMB + cc]) = hi;
            *reinterpret_cast<uint32_t*>(&Cl[r * EMB + cc]) = lo;
        }
    }
}

// ---------------------------------------------------------------------------
extern "C" void kernel_launch(void* const* d_in, const int* in_sizes, int n_in,
                              void* d_out, int out_size)
{
    const float* hs   = (const float*)d_in[0];
    const float* kv   = (const float*)d_in[1];
    const float* mask = (const float*)d_in[2];
    const float* hm   = (const float*)d_in[3];
    const float* Wq   = (const float*)d_in[4];
    const float* bq   = (const float*)d_in[5];
    const float* Wk   = (const float*)d_in[6];
    const float* bk   = (const float*)d_in[7];
    const float* Wv   = (const float*)d_in[8];
    const float* bv   = (const float*)d_in[9];
    const float* Wo   = (const float*)d_in[10];
    const float* bo   = (const float*)d_in[11];
    float* out = (float*)d_out;

    __nv_bfloat16 *HSh, *HSl, *KVh, *KVl;
    __nv_bfloat16 *Qh, *Ql, *Kh, *Kl, *Vh, *Vl, *Vth, *Vtl, *Ch, *Cl;
    __nv_bfloat16 *Wqh, *Wql, *Wkh, *Wkl, *Wvh, *Wvl, *Woh, *Wol;
    cudaGetSymbolAddress((void**)&HSh, g_HShi); cudaGetSymbolAddress((void**)&HSl, g_HSlo);
    cudaGetSymbolAddress((void**)&KVh, g_KVhi); cudaGetSymbolAddress((void**)&KVl, g_KVlo);
    cudaGetSymbolAddress((void**)&Qh, g_Qhi);  cudaGetSymbolAddress((void**)&Ql, g_Qlo);
    cudaGetSymbolAddress((void**)&Kh, g_Khi);  cudaGetSymbolAddress((void**)&Kl, g_Klo);
    cudaGetSymbolAddress((void**)&Vh, g_Vhi);  cudaGetSymbolAddress((void**)&Vl, g_Vlo);
    cudaGetSymbolAddress((void**)&Vth, g_Vthi); cudaGetSymbolAddress((void**)&Vtl, g_Vtlo);
    cudaGetSymbolAddress((void**)&Ch, g_Chi);  cudaGetSymbolAddress((void**)&Cl, g_Clo);
    cudaGetSymbolAddress((void**)&Wqh, g_Wqthi); cudaGetSymbolAddress((void**)&Wql, g_Wqtlo);
    cudaGetSymbolAddress((void**)&Wkh, g_Wkthi); cudaGetSymbolAddress((void**)&Wkl, g_Wktlo);
    cudaGetSymbolAddress((void**)&Wvh, g_Wvthi); cudaGetSymbolAddress((void**)&Wvl, g_Wvtlo);
    cudaGetSymbolAddress((void**)&Woh, g_Wothi); cudaGetSymbolAddress((void**)&Wol, g_Wotlo);

    cudaFuncSetAttribute(proj_nt<true>,  cudaFuncAttributeMaxDynamicSharedMemorySize, PROJ_SMEM);
    cudaFuncSetAttribute(proj_nt<false>, cudaFuncAttributeMaxDynamicSharedMemorySize, PROJ_SMEM);
    cudaFuncSetAttribute(flash_attn, cudaFuncAttributeMaxDynamicSharedMemorySize, FLASH_SMEM);

    // Split activations fp32 -> bf16 hi/lo
    split_act<<<(B * T * QIN / 4 + 255) / 256, 256>>>(hs, HSh, HSl, B * T * QIN / 4);
    split_act<<<(B * S * KVIN / 4 + 255) / 256, 256>>>(kv, KVh, KVl, B * S * KVIN / 4);

    // Weight transpose + split
    wsplit_t<<<dim3(EMB / 32, QIN / 32), 256>>>(Wq, QIN, EMB, Wqh, Wql);
    wsplit_t<<<dim3(EMB / 32, KVIN / 32), 256>>>(Wk, KVIN, EMB, Wkh, Wkl);
    wsplit_t<<<dim3(EMB / 32, KVIN / 32), 256>>>(Wv, KVIN, EMB, Wvh, Wvl);
    wsplit_t<<<dim3(EMB / 32, EMB / 32), 256>>>(Wo, EMB, EMB, Woh, Wol);

    // Projections -> split bf16
    proj_nt<true><<<dim3(EMB / 128, (B * T) / 128), 256, PROJ_SMEM>>>(
        QIN, HSh, HSl, QIN, Wqh, Wql, nullptr, Qh, Ql, EMB, bq, SCALING);
    proj_nt<true><<<dim3(EMB / 128, (B * S) / 128), 256, PROJ_SMEM>>>(
        KVIN, KVh, KVl, KVIN, Wkh, Wkl, nullptr, Kh, Kl, EMB, bk, 1.0f);
    proj_nt<true><<<dim3(EMB / 128, (B * S) / 128), 256, PROJ_SMEM>>>(
        KVIN, KVh, KVl, KVIN, Wvh, Wvl, nullptr, Vh, Vl, EMB, bv, 1.0f);

    // V transpose per head
    vtrans<<<dim3(S / 64, 1, B * H), 256>>>(Vh, Vl, Vth, Vtl);

    // Fused scores + softmax + PV
    flash_attn<<<dim3(T / 128, B * H), 256, FLASH_SMEM>>>(
        Qh, Ql, Kh, Kl, Vth, Vtl, mask, hm, Ch, Cl);

    // out = ctx @ Wo + bo
    proj_nt<false><<<dim3(EMB / 128, (B * T) / 128), 256, PROJ_SMEM>>>(
        EMB, Ch, Cl, EMB, Woh, Wol, out, nullptr, nullptr, EMB, bo, 1.0f);
}